// round 15
// baseline (speedup 1.0000x reference)
#include <cuda_runtime.h>
#include <cuda_fp8.h>
#include <stdint.h>

#define NR 8192
#define DD 512
#define BM 128
#define BKB 64               // k bytes (fp8 elems) per stage
#define NKT (DD / BKB)       // 8 k-tiles
#define NBLK (NR / BM)       // 64
#define NTRI (NBLK * (NBLK + 1) / 2)   // 2080 tiles
#define STAGES 4
#define SSTB 80                        // smem row stride bytes (conflict-free ldmatrix)
#define TILE_SMEM (BM * SSTB)          // 10240
#define STAGE_SMEM (2 * TILE_SMEM)     // 20480
#define SMEM_TOTAL (STAGES * STAGE_SMEM)  // 81920
#define RBLK 256                       // reduce blocks
#define NORMC 256                      // GEMM CTAs that also norm (32 rows each)

// ---- device scratch ----
__device__ __align__(16) uint8_t g_ne[NR * DD];   // e4m3 normalized embeddings
__device__ float g_pos[NR];
__device__ float g_Spart[NBLK][NR];
__device__ float g_blocksum[RBLK];
__device__ int g_cnt;           // zero-init; reduce resets each run
__device__ int g_flag[NBLK];    // per-128-row-block normed-row counters (to 128)

__device__ __forceinline__ int ld_acquire(const int* p) {
    int v;
    asm volatile("ld.acquire.gpu.global.b32 %0, [%1];" : "=r"(v) : "l"(p) : "memory");
    return v;
}

// ============================================================
// MMA / cp.async helpers
// ============================================================
__device__ __forceinline__ void ldsm_x4(uint32_t& r0, uint32_t& r1, uint32_t& r2, uint32_t& r3,
                                        uint32_t addr) {
    asm volatile("ldmatrix.sync.aligned.m8n8.x4.shared.b16 {%0,%1,%2,%3}, [%4];"
                 : "=r"(r0), "=r"(r1), "=r"(r2), "=r"(r3) : "r"(addr));
}
__device__ __forceinline__ void mma_fp8(float c[4], const uint32_t a[4], uint32_t b0, uint32_t b1) {
    asm volatile(
        "mma.sync.aligned.m16n8k32.row.col.f32.e4m3.e4m3.f32 "
        "{%0,%1,%2,%3}, {%4,%5,%6,%7}, {%8,%9}, {%0,%1,%2,%3};"
        : "+f"(c[0]), "+f"(c[1]), "+f"(c[2]), "+f"(c[3])
        : "r"(a[0]), "r"(a[1]), "r"(a[2]), "r"(a[3]), "r"(b0), "r"(b1));
}
__device__ __forceinline__ void cp16(uint32_t dst, const void* src) {
    asm volatile("cp.async.cg.shared.global [%0], [%1], 16;" :: "r"(dst), "l"(src));
}
__device__ __forceinline__ void cp_commit() {
    asm volatile("cp.async.commit_group;" ::: "memory");
}
template <int N>
__device__ __forceinline__ void cp_wait() {
    asm volatile("cp.async.wait_group %0;" :: "n"(N) : "memory");
}

// ============================================================
// Fused kernel: every CTA = one triangle tile (bj-major);
// CTAs 0..255 first normalize 32 rows each (full chip prologue).
// ============================================================
__global__ void __launch_bounds__(256, 2) gemm_lse_kernel(const float* __restrict__ emb,
                                                          const float* __restrict__ tgt) {
    extern __shared__ char smem[];
    const uint32_t sb = (uint32_t)__cvta_generic_to_shared(smem);
    const int tid = threadIdx.x;
    const int u = blockIdx.x;

    // ---------- norm prologue (CTAs 0..255, 32 rows each) ----------
    if (u < NORMC) {
        float* sred = (float*)smem;    // [2][3][4] floats
        const int h = tid >> 7;
        const int t = tid & 127;
        const int wh = (tid >> 5) & 3;
        const int l = tid & 31;
#pragma unroll
        for (int i = 0; i < 16; i++) {
            const int row = u * 32 + i * 2 + h;
            float4 a = reinterpret_cast<const float4*>(emb + (size_t)row * DD)[t];
            float4 b = reinterpret_cast<const float4*>(tgt + (size_t)row * DD)[t];

            float ee = a.x*a.x + a.y*a.y + a.z*a.z + a.w*a.w;
            float tt = b.x*b.x + b.y*b.y + b.z*b.z + b.w*b.w;
            float et = a.x*b.x + a.y*b.y + a.z*b.z + a.w*b.w;
#pragma unroll
            for (int o = 16; o > 0; o >>= 1) {
                ee += __shfl_xor_sync(0xFFFFFFFFu, ee, o);
                tt += __shfl_xor_sync(0xFFFFFFFFu, tt, o);
                et += __shfl_xor_sync(0xFFFFFFFFu, et, o);
            }
            if (l == 0) {
                sred[(h * 3 + 0) * 4 + wh] = ee;
                sred[(h * 3 + 1) * 4 + wh] = tt;
                sred[(h * 3 + 2) * 4 + wh] = et;
            }
            __syncthreads();
            ee = sred[(h*3+0)*4+0] + sred[(h*3+0)*4+1] + sred[(h*3+0)*4+2] + sred[(h*3+0)*4+3];
            tt = sred[(h*3+1)*4+0] + sred[(h*3+1)*4+1] + sred[(h*3+1)*4+2] + sred[(h*3+1)*4+3];
            et = sred[(h*3+2)*4+0] + sred[(h*3+2)*4+1] + sred[(h*3+2)*4+2] + sred[(h*3+2)*4+3];
            __syncthreads();

            float inv_e = rsqrtf(ee);
            if (t == 0) g_pos[row] = et * inv_e * rsqrtf(tt);

            uint16_t lo16, hi16;
            asm("cvt.rn.satfinite.e4m3x2.f32 %0, %1, %2;"
                : "=h"(lo16) : "f"(a.y * inv_e), "f"(a.x * inv_e));
            asm("cvt.rn.satfinite.e4m3x2.f32 %0, %1, %2;"
                : "=h"(hi16) : "f"(a.w * inv_e), "f"(a.z * inv_e));
            uint32_t p = (uint32_t)lo16 | ((uint32_t)hi16 << 16);
            reinterpret_cast<uint32_t*>(g_ne)[(size_t)row * (DD / 4) + t] = p;
        }
        __threadfence();
        __syncthreads();
        if (tid == 0) atomicAdd(&g_flag[u >> 2], 32);
    }

    // ---------- decode bj-major triangle index ----------
    const int lane = tid & 31;
    const int wid = tid >> 5;
    const int warp_m = wid >> 1;
    const int warp_n = wid & 1;
    const int ksel = wid & 1;

#define TRI2(b) ((b) * ((b) + 1) / 2)
    int bj = (int)((sqrtf(8.0f * (float)u + 1.0f) - 1.0f) * 0.5f);
    if (bj < 0) bj = 0;
    if (bj > 63) bj = 63;
    while (bj > 0 && TRI2(bj) > u) bj--;
    while (bj < 63 && TRI2(bj + 1) <= u) bj++;
    const int bi = u - TRI2(bj);
    const bool diag = (bi == bj);

    // ---------- wait for source blocks ----------
    if (tid == 0) {
        while (ld_acquire(&g_flag[bi]) != 128) __nanosleep(32);
        while (ld_acquire(&g_flag[bj]) != 128) __nanosleep(32);
    }
    __syncthreads();

    const uint8_t* gA = g_ne + (size_t)bi * BM * DD;
    const uint8_t* gB = g_ne + (size_t)bj * BM * DD;

    const int r0c = tid >> 2;
    const int r1c = (tid + 256) >> 2;
    const int kc0 = (tid & 3) * 16;

    const int lrow = lane & 15;
    const int lkb  = (lane >> 4) * 16;
    const uint32_t aoff0 = (uint32_t)((warp_m * 32 + lrow) * SSTB + lkb);
    const uint32_t aoff1 = aoff0 + 16 * SSTB;
    uint32_t boff[4];
#pragma unroll
    for (int nj = 0; nj < 4; nj++)
        boff[nj] = (uint32_t)((warp_n * 64 + nj * 16 + lrow) * SSTB + lkb) + TILE_SMEM;

    float acc[2][8][4];
#pragma unroll
    for (int mi = 0; mi < 2; mi++)
#pragma unroll
        for (int ni = 0; ni < 8; ni++)
#pragma unroll
            for (int k = 0; k < 4; k++) acc[mi][ni][k] = 0.f;

#pragma unroll
    for (int p = 0; p < STAGES - 1; p++) {
        uint32_t base = sb + p * STAGE_SMEM;
        cp16(base + r0c * SSTB + kc0, gA + (size_t)r0c * DD + p * BKB + kc0);
        cp16(base + r1c * SSTB + kc0, gA + (size_t)r1c * DD + p * BKB + kc0);
        cp16(base + TILE_SMEM + r0c * SSTB + kc0, gB + (size_t)r0c * DD + p * BKB + kc0);
        cp16(base + TILE_SMEM + r1c * SSTB + kc0, gB + (size_t)r1c * DD + p * BKB + kc0);
        cp_commit();
    }

#pragma unroll
    for (int kt = 0; kt < NKT; kt++) {
        cp_wait<STAGES - 2>();
        __syncthreads();

        uint32_t base = sb + (kt & (STAGES - 1)) * STAGE_SMEM;
        const uint32_t o0 = (uint32_t)ksel * 32;
        const uint32_t o1 = o0 ^ 32;

        uint32_t a[2][4], b[4][4];
        ldsm_x4(a[0][0], a[0][1], a[0][2], a[0][3], base + aoff0 + o0);
        ldsm_x4(a[1][0], a[1][1], a[1][2], a[1][3], base + aoff1 + o0);
#pragma unroll
        for (int nj = 0; nj < 4; nj++)
            ldsm_x4(b[nj][0], b[nj][1], b[nj][2], b[nj][3], base + boff[nj] + o0);

        if (kt + STAGES - 1 < NKT) {
            const int kl = kt + STAGES - 1;
            uint32_t lb = sb + (kl & (STAGES - 1)) * STAGE_SMEM;
            cp16(lb + r0c * SSTB + kc0, gA + (size_t)r0c * DD + kl * BKB + kc0);
            cp16(lb + r1c * SSTB + kc0, gA + (size_t)r1c * DD + kl * BKB + kc0);
            cp16(lb + TILE_SMEM + r0c * SSTB + kc0, gB + (size_t)r0c * DD + kl * BKB + kc0);
            cp16(lb + TILE_SMEM + r1c * SSTB + kc0, gB + (size_t)r1c * DD + kl * BKB + kc0);
        }
        cp_commit();

#pragma unroll
        for (int mi = 0; mi < 2; mi++)
#pragma unroll
            for (int ni = 0; ni < 8; ni++)
                mma_fp8(acc[mi][ni], a[mi], b[ni >> 1][ni & 1], b[ni >> 1][(ni & 1) + 2]);

        ldsm_x4(a[0][0], a[0][1], a[0][2], a[0][3], base + aoff0 + o1);
        ldsm_x4(a[1][0], a[1][1], a[1][2], a[1][3], base + aoff1 + o1);
#pragma unroll
        for (int nj = 0; nj < 4; nj++)
            ldsm_x4(b[nj][0], b[nj][1], b[nj][2], b[nj][3], base + boff[nj] + o1);
#pragma unroll
        for (int mi = 0; mi < 2; mi++)
#pragma unroll
            for (int ni = 0; ni < 8; ni++)
                mma_fp8(acc[mi][ni], a[mi], b[ni >> 1][ni & 1], b[ni >> 1][(ni & 1) + 2]);
    }

    // ---- epilogue ----
#pragma unroll
    for (int mi = 0; mi < 2; mi++)
#pragma unroll
        for (int ni = 0; ni < 8; ni++)
#pragma unroll
            for (int k = 0; k < 4; k++) {
                float x = acc[mi][ni][k];
                acc[mi][ni][k] = __expf(x + x);
            }

    float* rowbuf = (float*)smem;               // [2][128]
    float* colbuf = (float*)(smem + 1024);      // [4][128]
    __syncthreads();

#pragma unroll
    for (int mi = 0; mi < 2; mi++) {
        float r0 = 0.f, r1 = 0.f;
#pragma unroll
        for (int ni = 0; ni < 8; ni++) {
            r0 += acc[mi][ni][0] + acc[mi][ni][1];
            r1 += acc[mi][ni][2] + acc[mi][ni][3];
        }
        r0 += __shfl_xor_sync(0xFFFFFFFFu, r0, 1);
        r0 += __shfl_xor_sync(0xFFFFFFFFu, r0, 2);
        r1 += __shfl_xor_sync(0xFFFFFFFFu, r1, 1);
        r1 += __shfl_xor_sync(0xFFFFFFFFu, r1, 2);
        if ((lane & 3) == 0) {
            int rr = warp_m * 32 + mi * 16 + (lane >> 2);
            rowbuf[warp_n * 128 + rr] = r0;
            rowbuf[warp_n * 128 + rr + 8] = r1;
        }
    }

    if (!diag) {
#pragma unroll
        for (int ni = 0; ni < 8; ni++) {
            float ce = acc[0][ni][0] + acc[0][ni][2] + acc[1][ni][0] + acc[1][ni][2];
            float co = acc[0][ni][1] + acc[0][ni][3] + acc[1][ni][1] + acc[1][ni][3];
            ce += __shfl_xor_sync(0xFFFFFFFFu, ce, 4);
            ce += __shfl_xor_sync(0xFFFFFFFFu, ce, 8);
            ce += __shfl_xor_sync(0xFFFFFFFFu, ce, 16);
            co += __shfl_xor_sync(0xFFFFFFFFu, co, 4);
            co += __shfl_xor_sync(0xFFFFFFFFu, co, 8);
            co += __shfl_xor_sync(0xFFFFFFFFu, co, 16);
            if (lane < 4) {
                int cc = warp_n * 64 + ni * 8 + lane * 2;
                colbuf[warp_m * 128 + cc] = ce;
                colbuf[warp_m * 128 + cc + 1] = co;
            }
        }
    }
    __syncthreads();

    if (tid < 128) {
        g_Spart[bj][bi * BM + tid] = rowbuf[tid] + rowbuf[128 + tid];
        if (!diag)
            g_Spart[bi][bj * BM + tid] =
                colbuf[tid] + colbuf[128 + tid] + colbuf[256 + tid] + colbuf[384 + tid];
    }
}

// ============================================================
// Kernel C: coalesced per-row combine + final; resets flags for replay
// ============================================================
__global__ void reduce_kernel(float* __restrict__ out) {
    const int tid = threadIdx.x;
    const int wid = tid >> 5;
    const int lane = tid & 31;
    const int row = blockIdx.x * 32 + lane;

    float s = 0.f;
#pragma unroll
    for (int k = 0; k < 8; k++) s += g_Spart[wid * 8 + k][row];   // coalesced per warp

    __shared__ float sp[8][32];
    __shared__ int slast;
    sp[wid][lane] = s;
    __syncthreads();

    if (wid == 0) {
        float tot = sp[0][lane] + sp[1][lane] + sp[2][lane] + sp[3][lane]
                  + sp[4][lane] + sp[5][lane] + sp[6][lane] + sp[7][lane];
        float v = logf(tot) - 2.f * g_pos[row];
#pragma unroll
        for (int o = 16; o > 0; o >>= 1) v += __shfl_xor_sync(0xFFFFFFFFu, v, o);
        if (lane == 0) {
            g_blocksum[blockIdx.x] = v;
            __threadfence();
            int prev = atomicAdd(&g_cnt, 1);
            slast = (prev == RBLK - 1) ? 1 : 0;
        }
    }
    __syncthreads();
    if (slast) {
        if (tid >= 32 && tid < 96) g_flag[tid - 32] = 0;   // reset 64 ready-flags
        if (tid < 32) {
            __threadfence();
            float x = 0.f;
#pragma unroll
            for (int k = 0; k < RBLK / 32; k++) x += g_blocksum[tid * (RBLK / 32) + k];
#pragma unroll
            for (int o = 16; o > 0; o >>= 1) x += __shfl_xor_sync(0xFFFFFFFFu, x, o);
            if (tid == 0) {
                out[0] = x * (1.0f / (2.0f * NR));
                g_cnt = 0;
            }
        }
    }
}

// ============================================================
extern "C" void kernel_launch(void* const* d_in, const int* in_sizes, int n_in,
                              void* d_out, int out_size) {
    const float* emb = (const float*)d_in[0];
    const float* tgt = (const float*)d_in[1];
    float* out = (float*)d_out;

    cudaFuncSetAttribute(gemm_lse_kernel, cudaFuncAttributeMaxDynamicSharedMemorySize, SMEM_TOTAL);

    gemm_lse_kernel<<<NTRI, 256, SMEM_TOTAL>>>(emb, tgt);
    reduce_kernel<<<RBLK, 256>>>(out);
}

// round 16
// speedup vs baseline: 1.0678x; 1.0678x over previous
#include <cuda_runtime.h>
#include <cuda_fp8.h>
#include <stdint.h>

#define NR 8192
#define DD 512
#define BM 128
#define BKB 64               // k bytes (fp8 elems) per stage
#define NKT (DD / BKB)       // 8 k-tiles
#define NBLK (NR / BM)       // 64
#define NTRI (NBLK * (NBLK + 1) / 2)   // 2080 tiles
#define STAGES 4
#define SSTB 80                        // smem row stride bytes (conflict-free ldmatrix)
#define TILE_SMEM (BM * SSTB)          // 10240
#define STAGE_SMEM (2 * TILE_SMEM)     // 20480
#define SMEM_TOTAL (STAGES * STAGE_SMEM)  // 81920
#define RBLK 256                       // reduce blocks

// ---- device scratch ----
__device__ __align__(16) uint8_t g_ne[NR * DD];   // e4m3 normalized embeddings
__device__ float g_pos[NR];
__device__ float g_Spart[NBLK][NR];
__device__ float g_blocksum[RBLK];
__device__ int g_cnt;   // zero-init; self-resets each run

// ============================================================
// Kernel A: normalize -> e4m3. Warp per 2 rows; 16 LDG.128 in
// flight per thread (MLP 16); shfl-only reduce; no smem.
// ============================================================
__global__ void __launch_bounds__(256) norm_kernel(const float* __restrict__ emb,
                                                   const float* __restrict__ tgt) {
    const int w = threadIdx.x >> 5;
    const int l = threadIdx.x & 31;
    const int row0 = (blockIdx.x * 8 + w) * 2;   // grid = NR/16 = 512

    const float4* e0 = reinterpret_cast<const float4*>(emb + (size_t)row0 * DD);
    const float4* t0 = reinterpret_cast<const float4*>(tgt + (size_t)row0 * DD);
    const float4* e1 = e0 + DD / 4;
    const float4* t1 = t0 + DD / 4;

    float4 a0[4], a1[4], b0[4], b1[4];
#pragma unroll
    for (int j = 0; j < 4; j++) {
        a0[j] = __ldg(e0 + l + 32 * j);
        a1[j] = __ldg(e1 + l + 32 * j);
        b0[j] = __ldg(t0 + l + 32 * j);
        b1[j] = __ldg(t1 + l + 32 * j);
    }

    float ee0 = 0.f, tt0 = 0.f, et0 = 0.f, ee1 = 0.f, tt1 = 0.f, et1 = 0.f;
#pragma unroll
    for (int j = 0; j < 4; j++) {
        ee0 += a0[j].x*a0[j].x + a0[j].y*a0[j].y + a0[j].z*a0[j].z + a0[j].w*a0[j].w;
        tt0 += b0[j].x*b0[j].x + b0[j].y*b0[j].y + b0[j].z*b0[j].z + b0[j].w*b0[j].w;
        et0 += a0[j].x*b0[j].x + a0[j].y*b0[j].y + a0[j].z*b0[j].z + a0[j].w*b0[j].w;
        ee1 += a1[j].x*a1[j].x + a1[j].y*a1[j].y + a1[j].z*a1[j].z + a1[j].w*a1[j].w;
        tt1 += b1[j].x*b1[j].x + b1[j].y*b1[j].y + b1[j].z*b1[j].z + b1[j].w*b1[j].w;
        et1 += a1[j].x*b1[j].x + a1[j].y*b1[j].y + a1[j].z*b1[j].z + a1[j].w*b1[j].w;
    }
#pragma unroll
    for (int o = 16; o > 0; o >>= 1) {
        ee0 += __shfl_xor_sync(0xFFFFFFFFu, ee0, o);
        tt0 += __shfl_xor_sync(0xFFFFFFFFu, tt0, o);
        et0 += __shfl_xor_sync(0xFFFFFFFFu, et0, o);
        ee1 += __shfl_xor_sync(0xFFFFFFFFu, ee1, o);
        tt1 += __shfl_xor_sync(0xFFFFFFFFu, tt1, o);
        et1 += __shfl_xor_sync(0xFFFFFFFFu, et1, o);
    }

    float inv0 = rsqrtf(ee0);
    float inv1 = rsqrtf(ee1);
    if (l == 0) {
        g_pos[row0]     = et0 * inv0 * rsqrtf(tt0);
        g_pos[row0 + 1] = et1 * inv1 * rsqrtf(tt1);
    }

    uint32_t* o0 = reinterpret_cast<uint32_t*>(g_ne) + (size_t)row0 * (DD / 4);
    uint32_t* o1 = o0 + DD / 4;
#pragma unroll
    for (int j = 0; j < 4; j++) {
        uint16_t lo, hi;
        asm("cvt.rn.satfinite.e4m3x2.f32 %0, %1, %2;"
            : "=h"(lo) : "f"(a0[j].y * inv0), "f"(a0[j].x * inv0));
        asm("cvt.rn.satfinite.e4m3x2.f32 %0, %1, %2;"
            : "=h"(hi) : "f"(a0[j].w * inv0), "f"(a0[j].z * inv0));
        o0[l + 32 * j] = (uint32_t)lo | ((uint32_t)hi << 16);
        asm("cvt.rn.satfinite.e4m3x2.f32 %0, %1, %2;"
            : "=h"(lo) : "f"(a1[j].y * inv1), "f"(a1[j].x * inv1));
        asm("cvt.rn.satfinite.e4m3x2.f32 %0, %1, %2;"
            : "=h"(hi) : "f"(a1[j].w * inv1), "f"(a1[j].z * inv1));
        o1[l + 32 * j] = (uint32_t)lo | ((uint32_t)hi << 16);
    }
}

// ============================================================
// MMA / cp.async helpers
// ============================================================
__device__ __forceinline__ void ldsm_x4(uint32_t& r0, uint32_t& r1, uint32_t& r2, uint32_t& r3,
                                        uint32_t addr) {
    asm volatile("ldmatrix.sync.aligned.m8n8.x4.shared.b16 {%0,%1,%2,%3}, [%4];"
                 : "=r"(r0), "=r"(r1), "=r"(r2), "=r"(r3) : "r"(addr));
}
__device__ __forceinline__ void mma_fp8(float c[4], const uint32_t a[4], uint32_t b0, uint32_t b1) {
    asm volatile(
        "mma.sync.aligned.m16n8k32.row.col.f32.e4m3.e4m3.f32 "
        "{%0,%1,%2,%3}, {%4,%5,%6,%7}, {%8,%9}, {%0,%1,%2,%3};"
        : "+f"(c[0]), "+f"(c[1]), "+f"(c[2]), "+f"(c[3])
        : "r"(a[0]), "r"(a[1]), "r"(a[2]), "r"(a[3]), "r"(b0), "r"(b1));
}
__device__ __forceinline__ void cp16(uint32_t dst, const void* src) {
    asm volatile("cp.async.cg.shared.global [%0], [%1], 16;" :: "r"(dst), "l"(src));
}
__device__ __forceinline__ void cp_commit() {
    asm volatile("cp.async.commit_group;" ::: "memory");
}
template <int N>
__device__ __forceinline__ void cp_wait() {
    asm volatile("cp.async.wait_group %0;" :: "n"(N) : "memory");
}

// ============================================================
// Kernel B: upper-triangle fp8 GEMM + exp(2x) row/col sums  [R14, unchanged]
// ============================================================
__global__ void __launch_bounds__(256, 2) gemm_lse_kernel() {
    extern __shared__ char smem[];
    const uint32_t sb = (uint32_t)__cvta_generic_to_shared(smem);

    const int tid = threadIdx.x;
    const int lane = tid & 31;
    const int wid = tid >> 5;
    const int warp_m = wid >> 1;
    const int warp_n = wid & 1;
    const int ksel = wid & 1;

    int t = blockIdx.x;
    int bi = (int)(64.5f - sqrtf(64.5f * 64.5f - 2.0f * (float)t));
    if (bi < 0) bi = 0;
    if (bi > 63) bi = 63;
#define TRI_S(b) ((b) * 64 - ((b) * ((b) - 1)) / 2)
    while (bi > 0 && TRI_S(bi) > t) bi--;
    while (bi < 63 && TRI_S(bi + 1) <= t) bi++;
    const int bj = bi + (t - TRI_S(bi));
    const bool diag = (bi == bj);

    const uint8_t* gA = g_ne + (size_t)bi * BM * DD;
    const uint8_t* gB = g_ne + (size_t)bj * BM * DD;

    const int r0c = tid >> 2;
    const int r1c = (tid + 256) >> 2;
    const int kc0 = (tid & 3) * 16;

    const int lrow = lane & 15;
    const int lkb  = (lane >> 4) * 16;
    const uint32_t aoff0 = (uint32_t)((warp_m * 32 + lrow) * SSTB + lkb);
    const uint32_t aoff1 = aoff0 + 16 * SSTB;
    uint32_t boff[4];
#pragma unroll
    for (int nj = 0; nj < 4; nj++)
        boff[nj] = (uint32_t)((warp_n * 64 + nj * 16 + lrow) * SSTB + lkb) + TILE_SMEM;

    float acc[2][8][4];
#pragma unroll
    for (int mi = 0; mi < 2; mi++)
#pragma unroll
        for (int ni = 0; ni < 8; ni++)
#pragma unroll
            for (int k = 0; k < 4; k++) acc[mi][ni][k] = 0.f;

#pragma unroll
    for (int p = 0; p < STAGES - 1; p++) {
        uint32_t base = sb + p * STAGE_SMEM;
        cp16(base + r0c * SSTB + kc0, gA + (size_t)r0c * DD + p * BKB + kc0);
        cp16(base + r1c * SSTB + kc0, gA + (size_t)r1c * DD + p * BKB + kc0);
        cp16(base + TILE_SMEM + r0c * SSTB + kc0, gB + (size_t)r0c * DD + p * BKB + kc0);
        cp16(base + TILE_SMEM + r1c * SSTB + kc0, gB + (size_t)r1c * DD + p * BKB + kc0);
        cp_commit();
    }

#pragma unroll
    for (int kt = 0; kt < NKT; kt++) {
        cp_wait<STAGES - 2>();
        __syncthreads();

        uint32_t base = sb + (kt & (STAGES - 1)) * STAGE_SMEM;
        const uint32_t o0 = (uint32_t)ksel * 32;
        const uint32_t o1 = o0 ^ 32;

        uint32_t a[2][4], b[4][4];
        ldsm_x4(a[0][0], a[0][1], a[0][2], a[0][3], base + aoff0 + o0);
        ldsm_x4(a[1][0], a[1][1], a[1][2], a[1][3], base + aoff1 + o0);
#pragma unroll
        for (int nj = 0; nj < 4; nj++)
            ldsm_x4(b[nj][0], b[nj][1], b[nj][2], b[nj][3], base + boff[nj] + o0);

        if (kt + STAGES - 1 < NKT) {
            const int kl = kt + STAGES - 1;
            uint32_t lb = sb + (kl & (STAGES - 1)) * STAGE_SMEM;
            cp16(lb + r0c * SSTB + kc0, gA + (size_t)r0c * DD + kl * BKB + kc0);
            cp16(lb + r1c * SSTB + kc0, gA + (size_t)r1c * DD + kl * BKB + kc0);
            cp16(lb + TILE_SMEM + r0c * SSTB + kc0, gB + (size_t)r0c * DD + kl * BKB + kc0);
            cp16(lb + TILE_SMEM + r1c * SSTB + kc0, gB + (size_t)r1c * DD + kl * BKB + kc0);
        }
        cp_commit();

#pragma unroll
        for (int mi = 0; mi < 2; mi++)
#pragma unroll
            for (int ni = 0; ni < 8; ni++)
                mma_fp8(acc[mi][ni], a[mi], b[ni >> 1][ni & 1], b[ni >> 1][(ni & 1) + 2]);

        ldsm_x4(a[0][0], a[0][1], a[0][2], a[0][3], base + aoff0 + o1);
        ldsm_x4(a[1][0], a[1][1], a[1][2], a[1][3], base + aoff1 + o1);
#pragma unroll
        for (int nj = 0; nj < 4; nj++)
            ldsm_x4(b[nj][0], b[nj][1], b[nj][2], b[nj][3], base + boff[nj] + o1);
#pragma unroll
        for (int mi = 0; mi < 2; mi++)
#pragma unroll
            for (int ni = 0; ni < 8; ni++)
                mma_fp8(acc[mi][ni], a[mi], b[ni >> 1][ni & 1], b[ni >> 1][(ni & 1) + 2]);
    }

    // ---- epilogue ----
#pragma unroll
    for (int mi = 0; mi < 2; mi++)
#pragma unroll
        for (int ni = 0; ni < 8; ni++)
#pragma unroll
            for (int k = 0; k < 4; k++) {
                float x = acc[mi][ni][k];
                acc[mi][ni][k] = __expf(x + x);
            }

    float* rowbuf = (float*)smem;               // [2][128]
    float* colbuf = (float*)(smem + 1024);      // [4][128]
    __syncthreads();

#pragma unroll
    for (int mi = 0; mi < 2; mi++) {
        float r0 = 0.f, r1 = 0.f;
#pragma unroll
        for (int ni = 0; ni < 8; ni++) {
            r0 += acc[mi][ni][0] + acc[mi][ni][1];
            r1 += acc[mi][ni][2] + acc[mi][ni][3];
        }
        r0 += __shfl_xor_sync(0xFFFFFFFFu, r0, 1);
        r0 += __shfl_xor_sync(0xFFFFFFFFu, r0, 2);
        r1 += __shfl_xor_sync(0xFFFFFFFFu, r1, 1);
        r1 += __shfl_xor_sync(0xFFFFFFFFu, r1, 2);
        if ((lane & 3) == 0) {
            int rr = warp_m * 32 + mi * 16 + (lane >> 2);
            rowbuf[warp_n * 128 + rr] = r0;
            rowbuf[warp_n * 128 + rr + 8] = r1;
        }
    }

    if (!diag) {
#pragma unroll
        for (int ni = 0; ni < 8; ni++) {
            float ce = acc[0][ni][0] + acc[0][ni][2] + acc[1][ni][0] + acc[1][ni][2];
            float co = acc[0][ni][1] + acc[0][ni][3] + acc[1][ni][1] + acc[1][ni][3];
            ce += __shfl_xor_sync(0xFFFFFFFFu, ce, 4);
            ce += __shfl_xor_sync(0xFFFFFFFFu, ce, 8);
            ce += __shfl_xor_sync(0xFFFFFFFFu, ce, 16);
            co += __shfl_xor_sync(0xFFFFFFFFu, co, 4);
            co += __shfl_xor_sync(0xFFFFFFFFu, co, 8);
            co += __shfl_xor_sync(0xFFFFFFFFu, co, 16);
            if (lane < 4) {
                int cc = warp_n * 64 + ni * 8 + lane * 2;
                colbuf[warp_m * 128 + cc] = ce;
                colbuf[warp_m * 128 + cc + 1] = co;
            }
        }
    }
    __syncthreads();

    if (tid < 128) {
        g_Spart[bj][bi * BM + tid] = rowbuf[tid] + rowbuf[128 + tid];
        if (!diag)
            g_Spart[bi][bj * BM + tid] =
                colbuf[tid] + colbuf[128 + tid] + colbuf[256 + tid] + colbuf[384 + tid];
    }
}

// ============================================================
// Kernel C: coalesced per-row combine + final  [R13, unchanged]
// ============================================================
__global__ void reduce_kernel(float* __restrict__ out) {
    const int tid = threadIdx.x;
    const int wid = tid >> 5;
    const int lane = tid & 31;
    const int row = blockIdx.x * 32 + lane;

    float s = 0.f;
#pragma unroll
    for (int k = 0; k < 8; k++) s += g_Spart[wid * 8 + k][row];   // coalesced per warp

    __shared__ float sp[8][32];
    __shared__ int slast;
    sp[wid][lane] = s;
    __syncthreads();

    if (wid == 0) {
        float tot = sp[0][lane] + sp[1][lane] + sp[2][lane] + sp[3][lane]
                  + sp[4][lane] + sp[5][lane] + sp[6][lane] + sp[7][lane];
        float v = logf(tot) - 2.f * g_pos[row];
#pragma unroll
        for (int o = 16; o > 0; o >>= 1) v += __shfl_xor_sync(0xFFFFFFFFu, v, o);
        if (lane == 0) {
            g_blocksum[blockIdx.x] = v;
            __threadfence();
            int prev = atomicAdd(&g_cnt, 1);
            slast = (prev == RBLK - 1) ? 1 : 0;
        }
    }
    __syncthreads();
    if (slast && tid < 32) {
        __threadfence();
        float x = 0.f;
#pragma unroll
        for (int k = 0; k < RBLK / 32; k++) x += g_blocksum[tid * (RBLK / 32) + k];
#pragma unroll
        for (int o = 16; o > 0; o >>= 1) x += __shfl_xor_sync(0xFFFFFFFFu, x, o);
        if (tid == 0) {
            out[0] = x * (1.0f / (2.0f * NR));
            g_cnt = 0;   // reset for next graph replay
        }
    }
}

// ============================================================
extern "C" void kernel_launch(void* const* d_in, const int* in_sizes, int n_in,
                              void* d_out, int out_size) {
    const float* emb = (const float*)d_in[0];
    const float* tgt = (const float*)d_in[1];
    float* out = (float*)d_out;

    cudaFuncSetAttribute(gemm_lse_kernel, cudaFuncAttributeMaxDynamicSharedMemorySize, SMEM_TOTAL);

    norm_kernel<<<NR / 16, 256>>>(emb, tgt);
    gemm_lse_kernel<<<NTRI, 256, SMEM_TOTAL>>>();
    reduce_kernel<<<RBLK, 256>>>(out);
}